// round 5
// baseline (speedup 1.0000x reference)
#include <cuda_runtime.h>
#include <cstdint>

// ---------------------------------------------------------------------------
// C=12, L=32, D=32, NOUT=2. Counts are int32 on device (JAX x64-off).
// Phase 1: dense per-read  q[r][2] = W2_s . relu(W x_r + b) summed over L.
// Phase 2: tiny ragged reduce of q over each allele + normalize + bias.
// ---------------------------------------------------------------------------

#define MAXR 131072
__device__ float2 g_q0[MAXR];   // per-read head partials, source 0
__device__ float2 g_q1[MAXR];   // per-read head partials, source 1

__device__ __forceinline__ uint32_t f2tf32(float f) {
    uint32_t u;
    asm("cvt.rna.tf32.f32 %0, %1;" : "=r"(u) : "f"(f));
    return u;
}

__device__ __forceinline__ void mma_tf32(float c[4], const uint32_t a[4],
                                         uint32_t b0, uint32_t b1) {
    asm volatile(
        "mma.sync.aligned.m16n8k8.row.col.f32.tf32.tf32.f32 "
        "{%0,%1,%2,%3},{%4,%5,%6,%7},{%8,%9},{%0,%1,%2,%3};"
        : "+f"(c[0]), "+f"(c[1]), "+f"(c[2]), "+f"(c[3])
        : "r"(a[0]), "r"(a[1]), "r"(a[2]), "r"(a[3]), "r"(b0), "r"(b1));
}

// ---------------------------------------------------------------------------
// Phase 1: grid-stride over reads; blockIdx.y = source. Per warp per read:
//   LDG.128 x3 (512B contiguous each) -> STS.128 x3 (XOR swizzle) ->
//   LDS.128 x3 -> 16 tf32 MMAs -> relu+col-sum -> warp fold -> W2 head ->
//   one STG.64 (float2). Double-buffered smem, one syncwarp per iteration.
// ---------------------------------------------------------------------------
__global__ __launch_bounds__(256) void rc_phase1(
    const float* __restrict__ t0, const float* __restrict__ t1,
    const float* __restrict__ W0, const float* __restrict__ b0,
    const float* __restrict__ W1, const float* __restrict__ b1,
    const float* __restrict__ W2, int R)
{
    const int s = blockIdx.y;
    const float* T  = s ? t1 : t0;
    const float* W  = s ? W1 : W0;
    const float* Bv = s ? b1 : b0;
    float2* Out     = s ? g_q1 : g_q0;

    const int tid  = threadIdx.x;
    const int wid  = tid >> 5, lane = tid & 31;
    const int qp   = lane >> 2, rp = lane & 3;   // MMA fragment coords
    const int g    = lane >> 3, h = lane & 7;    // staging coords

    __shared__ float4 buf[8][2][96];             // per-warp double buffer

    // A fragments af[m_tile][k_step][0..3] (bias rides channel c==12)
    uint32_t af[2][2][4];
    #pragma unroll
    for (int m = 0; m < 2; m++) {
        int r0 = qp + 16 * m, r1 = r0 + 8;
        af[m][0][0] = f2tf32(W[r0 * 12 + rp]);
        af[m][0][1] = f2tf32(W[r1 * 12 + rp]);
        af[m][0][2] = f2tf32(W[r0 * 12 + rp + 4]);
        af[m][0][3] = f2tf32(W[r1 * 12 + rp + 4]);
        af[m][1][0] = f2tf32(W[r0 * 12 + rp + 8]);
        af[m][1][1] = f2tf32(W[r1 * 12 + rp + 8]);
        af[m][1][2] = (rp == 0) ? f2tf32(Bv[r0]) : 0u;
        af[m][1][3] = (rp == 0) ? f2tf32(Bv[r1]) : 0u;
    }
    const uint32_t bk1 = (rp == 0) ? f2tf32(1.0f) : 0u;

    // W2 head weights for this lane's d-slots (d = 8i + qp), per output n
    float w2a[4], w2b[4];
    #pragma unroll
    for (int i = 0; i < 4; i++) {
        w2a[i] = W2[s * 32 + 8 * i + qp];         // n = 0
        w2b[i] = W2[64 + s * 32 + 8 * i + qp];    // n = 1
    }

    // swizzled float4 slot indices (12 rows x 8 slots per read)
    const int sw_st = h ^ (2 * g);
    const int sts0 = g * 8 + sw_st, sts1 = (g + 4) * 8 + sw_st,
              sts2 = (g + 8) * 8 + sw_st;
    const int sw_ld = qp ^ (2 * rp);
    const int lds0 = rp * 8 + sw_ld, lds1 = (rp + 4) * 8 + sw_ld,
              lds2 = (rp + 8) * 8 + sw_ld;

    const int WT = gridDim.x * 8;
    int r = blockIdx.x * 8 + wid;

    float4 A0, A1, A2;
    if (r < R) {
        const float4* p = (const float4*)T + (size_t)r * 96;
        A0 = p[g * 8 + h]; A1 = p[(g + 4) * 8 + h]; A2 = p[(g + 8) * 8 + h];
    }
    int pp = 0;
    while (r < R) {
        float4* B = buf[wid][pp];
        B[sts0] = A0; B[sts1] = A1; B[sts2] = A2;
        const int rn = r + WT;
        if (rn < R) {
            const float4* p = (const float4*)T + (size_t)rn * 96;
            A0 = p[g * 8 + h]; A1 = p[(g + 4) * 8 + h]; A2 = p[(g + 8) * 8 + h];
        }
        __syncwarp();

        float4 x0 = B[lds0], x1 = B[lds1], x2 = B[lds2];
        uint32_t u0[4] = {f2tf32(x0.x), f2tf32(x0.y), f2tf32(x0.z), f2tf32(x0.w)};
        uint32_t u1[4] = {f2tf32(x1.x), f2tf32(x1.y), f2tf32(x1.z), f2tf32(x1.w)};
        uint32_t u2[4] = {f2tf32(x2.x), f2tf32(x2.y), f2tf32(x2.z), f2tf32(x2.w)};

        float acc[4] = {0.f, 0.f, 0.f, 0.f};
        #pragma unroll
        for (int j = 0; j < 4; j++) {
            #pragma unroll
            for (int m = 0; m < 2; m++) {
                float c[4] = {0.f, 0.f, 0.f, 0.f};
                mma_tf32(c, af[m][0], u0[j], u1[j]);
                mma_tf32(c, af[m][1], u2[j], bk1);
                acc[2 * m]     += fmaxf(c[0], 0.f) + fmaxf(c[1], 0.f);
                acc[2 * m + 1] += fmaxf(c[2], 0.f) + fmaxf(c[3], 0.f);
            }
        }
        // fold over rp (columns): every lane gets y[d = 8i+qp]
        #pragma unroll
        for (int i = 0; i < 4; i++) {
            acc[i] += __shfl_xor_sync(0xffffffffu, acc[i], 1);
            acc[i] += __shfl_xor_sync(0xffffffffu, acc[i], 2);
        }
        // fold W2 head: q_n = sum_d y_d * W2[n, 32s+d]
        float q0 = acc[0] * w2a[0] + acc[1] * w2a[1]
                 + acc[2] * w2a[2] + acc[3] * w2a[3];
        float q1 = acc[0] * w2b[0] + acc[1] * w2b[1]
                 + acc[2] * w2b[2] + acc[3] * w2b[3];
        #pragma unroll
        for (int o = 4; o <= 16; o <<= 1) {        // fold over qp
            q0 += __shfl_xor_sync(0xffffffffu, q0, o);
            q1 += __shfl_xor_sync(0xffffffffu, q1, o);
        }
        if (lane == 0) Out[r] = make_float2(q0, q1);

        r = rn; pp ^= 1;
    }
}

// ---------------------------------------------------------------------------
// Phase 2: one warp per allele (8 per block). Block computes its own base
// offsets by grid-striding the count arrays; warps read ~cnt float2 each.
// ---------------------------------------------------------------------------
__global__ __launch_bounds__(256) void rc_phase2(
    const int* __restrict__ cnt0, const int* __restrict__ cnt1,
    const float* __restrict__ dm0, const float* __restrict__ dm1,
    const float* __restrict__ b2, float* __restrict__ out, int A)
{
    const int tid = threadIdx.x, wid = tid >> 5, lane = tid & 31;
    const int aBase = blockIdx.x * 8;

    __shared__ int sred[2][8];
    __shared__ int sOff[2];

    int a0 = 0, a1 = 0;
    for (int i = tid; i < aBase; i += 256) { a0 += cnt0[i]; a1 += cnt1[i]; }
    #pragma unroll
    for (int o = 16; o; o >>= 1) {
        a0 += __shfl_xor_sync(0xffffffffu, a0, o);
        a1 += __shfl_xor_sync(0xffffffffu, a1, o);
    }
    if (lane == 0) { sred[0][wid] = a0; sred[1][wid] = a1; }
    __syncthreads();
    if (tid == 0) {
        int t0 = 0, t1 = 0;
        #pragma unroll
        for (int i = 0; i < 8; i++) { t0 += sred[0][i]; t1 += sred[1][i]; }
        sOff[0] = t0; sOff[1] = t1;
    }
    __syncthreads();

    const int a = aBase + wid;
    if (a >= A) return;

    int off0 = sOff[0], off1 = sOff[1];
    for (int i = 0; i < wid; i++) { off0 += cnt0[aBase + i]; off1 += cnt1[aBase + i]; }
    const int c0 = cnt0[a], c1 = cnt1[a];

    float s00 = 0.f, s01 = 0.f, s10 = 0.f, s11 = 0.f;
    for (int i = lane; i < c0; i += 32) {
        float2 v = g_q0[off0 + i]; s00 += v.x; s01 += v.y;
    }
    for (int i = lane; i < c1; i += 32) {
        float2 v = g_q1[off1 + i]; s10 += v.x; s11 += v.y;
    }
    #pragma unroll
    for (int o = 16; o; o >>= 1) {
        s00 += __shfl_xor_sync(0xffffffffu, s00, o);
        s01 += __shfl_xor_sync(0xffffffffu, s01, o);
        s10 += __shfl_xor_sync(0xffffffffu, s10, o);
        s11 += __shfl_xor_sync(0xffffffffu, s11, o);
    }
    if (lane == 0) {
        const float n0 = 1.0f / (dm0[a] * 32.f);
        const float n1 = 1.0f / (dm1[a] * 32.f);
        out[2 * a]     = b2[0] + s00 * n0 + s10 * n1;
        out[2 * a + 1] = b2[1] + s01 * n0 + s11 * n1;
    }
}

// ---------------------------------------------------------------------------
extern "C" void kernel_launch(void* const* d_in, const int* in_sizes, int n_in,
                              void* d_out, int out_size) {
    const float* t0  = (const float*)d_in[0];
    const float* t1  = (const float*)d_in[1];
    const float* W0  = (const float*)d_in[2];
    const float* b0  = (const float*)d_in[3];
    const float* W1  = (const float*)d_in[4];
    const float* b1  = (const float*)d_in[5];
    const float* W2  = (const float*)d_in[6];
    const float* b2  = (const float*)d_in[7];
    const int*   c0  = (const int*)d_in[8];
    const int*   c1  = (const int*)d_in[9];
    const float* dm0 = (const float*)d_in[11];
    const float* dm1 = (const float*)d_in[12];
    float* out = (float*)d_out;

    const int A = in_sizes[8];
    const int R = in_sizes[0] / 384;   // reads per source (C*L = 384)

    dim3 grid1(1024, 2);
    rc_phase1<<<grid1, 256>>>(t0, t1, W0, b0, W1, b1, W2, R);
    rc_phase2<<<(A + 7) / 8, 256>>>(c0, c1, dm0, dm1, b2, out, A);
}

// round 6
// speedup vs baseline: 1.0295x; 1.0295x over previous
#include <cuda_runtime.h>
#include <cstdint>

// ---------------------------------------------------------------------------
// C=12, L=32, D=32, NOUT=2. Counts are int32 on device (JAX x64-off).
// Phase 1: dense per-read  q[r][2] = W2_s . relu(W x_r + b) summed over L,
//          cp.async 3-stage per-warp pipeline.
// Phase 2: one thread per allele; block-scan offsets; tiny ragged reduce.
// ---------------------------------------------------------------------------

#define MAXR 131072
__device__ float2 g_q0[MAXR];
__device__ float2 g_q1[MAXR];

__device__ __forceinline__ uint32_t f2tf32(float f) {
    uint32_t u;
    asm("cvt.rna.tf32.f32 %0, %1;" : "=r"(u) : "f"(f));
    return u;
}

__device__ __forceinline__ void mma_tf32(float c[4], const uint32_t a[4],
                                         uint32_t b0, uint32_t b1) {
    asm volatile(
        "mma.sync.aligned.m16n8k8.row.col.f32.tf32.tf32.f32 "
        "{%0,%1,%2,%3},{%4,%5,%6,%7},{%8,%9},{%0,%1,%2,%3};"
        : "+f"(c[0]), "+f"(c[1]), "+f"(c[2]), "+f"(c[3])
        : "r"(a[0]), "r"(a[1]), "r"(a[2]), "r"(a[3]), "r"(b0), "r"(b1));
}

__device__ __forceinline__ void cp16(uint32_t smem_addr, const void* g) {
    asm volatile("cp.async.ca.shared.global [%0], [%1], 16;"
                 :: "r"(smem_addr), "l"(g));
}

// ---------------------------------------------------------------------------
// Phase 1. blockIdx.y = source. Per warp per read (1536B):
//   3x cp.async (512B ea, XOR-swizzled dst) -> wait_group/syncwarp ->
//   3x LDS.128 -> 12 cvt -> 16 tf32 MMAs -> relu+col-sum -> warp folds ->
//   W2 head fold -> one STG.64.
// ---------------------------------------------------------------------------
__global__ __launch_bounds__(256) void rc_phase1(
    const float* __restrict__ t0, const float* __restrict__ t1,
    const float* __restrict__ W0, const float* __restrict__ b0,
    const float* __restrict__ W1, const float* __restrict__ b1,
    const float* __restrict__ W2, int R)
{
    const int s = blockIdx.y;
    const float* T  = s ? t1 : t0;
    const float* W  = s ? W1 : W0;
    const float* Bv = s ? b1 : b0;
    float2* Out     = s ? g_q1 : g_q0;

    const int tid  = threadIdx.x;
    const int wid  = tid >> 5, lane = tid & 31;
    const int qp   = lane >> 2, rp = lane & 3;   // MMA fragment coords
    const int g    = lane >> 3, h = lane & 7;    // staging coords

    __shared__ float4 buf[8][3][96];             // per-warp 3-stage ring, 36KB

    // A fragments (bias rides channel c==12)
    uint32_t af[2][2][4];
    #pragma unroll
    for (int m = 0; m < 2; m++) {
        int r0 = qp + 16 * m, r1 = r0 + 8;
        af[m][0][0] = f2tf32(W[r0 * 12 + rp]);
        af[m][0][1] = f2tf32(W[r1 * 12 + rp]);
        af[m][0][2] = f2tf32(W[r0 * 12 + rp + 4]);
        af[m][0][3] = f2tf32(W[r1 * 12 + rp + 4]);
        af[m][1][0] = f2tf32(W[r0 * 12 + rp + 8]);
        af[m][1][1] = f2tf32(W[r1 * 12 + rp + 8]);
        af[m][1][2] = (rp == 0) ? f2tf32(Bv[r0]) : 0u;
        af[m][1][3] = (rp == 0) ? f2tf32(Bv[r1]) : 0u;
    }
    const uint32_t bk1 = (rp == 0) ? f2tf32(1.0f) : 0u;

    // W2 head weights for this lane's d-slots (d = 8i + qp)
    float w2a[4], w2b[4];
    #pragma unroll
    for (int i = 0; i < 4; i++) {
        w2a[i] = W2[s * 32 + 8 * i + qp];
        w2b[i] = W2[64 + s * 32 + 8 * i + qp];
    }

    // swizzled float4 slot indices (12 rows x 8 slots per read)
    const int sw_st = h ^ (2 * g);
    const int sts0 = g * 8 + sw_st, sts1 = (g + 4) * 8 + sw_st,
              sts2 = (g + 8) * 8 + sw_st;
    const int sw_ld = qp ^ (2 * rp);
    const int lds0 = rp * 8 + sw_ld, lds1 = (rp + 4) * 8 + sw_ld,
              lds2 = (rp + 8) * 8 + sw_ld;

    // per-lane cp.async destination addresses for each stage
    uint32_t dst[3][3];
    #pragma unroll
    for (int st = 0; st < 3; st++) {
        dst[st][0] = (uint32_t)__cvta_generic_to_shared(&buf[wid][st][sts0]);
        dst[st][1] = (uint32_t)__cvta_generic_to_shared(&buf[wid][st][sts1]);
        dst[st][2] = (uint32_t)__cvta_generic_to_shared(&buf[wid][st][sts2]);
    }

    const int WT = gridDim.x * 8;
    const int r0w = blockIdx.x * 8 + wid;

    // prologue: stages 0,1 for reads r0w, r0w+WT
    #pragma unroll
    for (int st = 0; st < 2; st++) {
        int rr = r0w + st * WT;
        if (rr < R) {
            const float4* p = (const float4*)T + (size_t)rr * 96;
            cp16(dst[st][0], p + g * 8 + h);
            cp16(dst[st][1], p + (g + 4) * 8 + h);
            cp16(dst[st][2], p + (g + 8) * 8 + h);
        }
        asm volatile("cp.async.commit_group;" ::: "memory");
    }

    int r = r0w, stage = 0;
    while (r < R) {
        // issue stage+2 (read r+2*WT), keep 2 groups in flight
        {
            int rr = r + 2 * WT;
            int st = stage + 2; if (st >= 3) st -= 3;
            if (rr < R) {
                const float4* p = (const float4*)T + (size_t)rr * 96;
                cp16(dst[st][0], p + g * 8 + h);
                cp16(dst[st][1], p + (g + 4) * 8 + h);
                cp16(dst[st][2], p + (g + 8) * 8 + h);
            }
            asm volatile("cp.async.commit_group;" ::: "memory");
        }
        asm volatile("cp.async.wait_group 2;" ::: "memory");
        __syncwarp();

        const float4* B = buf[wid][stage];
        float4 x0 = B[lds0], x1 = B[lds1], x2 = B[lds2];
        uint32_t u0[4] = {f2tf32(x0.x), f2tf32(x0.y), f2tf32(x0.z), f2tf32(x0.w)};
        uint32_t u1[4] = {f2tf32(x1.x), f2tf32(x1.y), f2tf32(x1.z), f2tf32(x1.w)};
        uint32_t u2[4] = {f2tf32(x2.x), f2tf32(x2.y), f2tf32(x2.z), f2tf32(x2.w)};

        float acc[4] = {0.f, 0.f, 0.f, 0.f};
        #pragma unroll
        for (int j = 0; j < 4; j++) {
            #pragma unroll
            for (int m = 0; m < 2; m++) {
                float c[4] = {0.f, 0.f, 0.f, 0.f};
                mma_tf32(c, af[m][0], u0[j], u1[j]);
                mma_tf32(c, af[m][1], u2[j], bk1);
                acc[2 * m]     += fmaxf(c[0], 0.f) + fmaxf(c[1], 0.f);
                acc[2 * m + 1] += fmaxf(c[2], 0.f) + fmaxf(c[3], 0.f);
            }
        }
        #pragma unroll
        for (int i = 0; i < 4; i++) {          // fold over rp (columns)
            acc[i] += __shfl_xor_sync(0xffffffffu, acc[i], 1);
            acc[i] += __shfl_xor_sync(0xffffffffu, acc[i], 2);
        }
        float q0 = acc[0] * w2a[0] + acc[1] * w2a[1]
                 + acc[2] * w2a[2] + acc[3] * w2a[3];
        float q1 = acc[0] * w2b[0] + acc[1] * w2b[1]
                 + acc[2] * w2b[2] + acc[3] * w2b[3];
        #pragma unroll
        for (int o = 4; o <= 16; o <<= 1) {    // fold over qp
            q0 += __shfl_xor_sync(0xffffffffu, q0, o);
            q1 += __shfl_xor_sync(0xffffffffu, q1, o);
        }
        if (lane == 0) Out[r] = make_float2(q0, q1);

        r += WT;
        stage++; if (stage >= 3) stage = 0;
    }
}

// ---------------------------------------------------------------------------
// Phase 2: one THREAD per allele (block = 256 alleles). Base offsets via
// grid-stride reduce; intra-block offsets via Hillis-Steele scan in smem.
// Each thread sums its cnt float2's sequentially (deterministic).
// ---------------------------------------------------------------------------
__global__ __launch_bounds__(256) void rc_phase2(
    const int* __restrict__ cnt0, const int* __restrict__ cnt1,
    const float* __restrict__ dm0, const float* __restrict__ dm1,
    const float* __restrict__ b2, float* __restrict__ out, int A)
{
    const int tid = threadIdx.x;
    const int aBase = blockIdx.x * 256;
    const int a = aBase + tid;

    __shared__ int r0[256], r1[256];

    // base = sum of counts before aBase
    int b0s = 0, b1s = 0;
    for (int i = tid; i < aBase; i += 256) { b0s += cnt0[i]; b1s += cnt1[i]; }
    r0[tid] = b0s; r1[tid] = b1s;
    __syncthreads();
    #pragma unroll
    for (int o = 128; o; o >>= 1) {
        if (tid < o) { r0[tid] += r0[tid + o]; r1[tid] += r1[tid + o]; }
        __syncthreads();
    }
    const int base0 = r0[0], base1 = r1[0];
    __syncthreads();

    const int c0 = (a < A) ? cnt0[a] : 0;
    const int c1 = (a < A) ? cnt1[a] : 0;

    // inclusive scan of counts within block
    r0[tid] = c0; r1[tid] = c1;
    __syncthreads();
    #pragma unroll
    for (int o = 1; o < 256; o <<= 1) {
        int v0 = (tid >= o) ? r0[tid - o] : 0;
        int v1 = (tid >= o) ? r1[tid - o] : 0;
        __syncthreads();
        r0[tid] += v0; r1[tid] += v1;
        __syncthreads();
    }
    if (a >= A) return;
    const int off0 = base0 + r0[tid] - c0;
    const int off1 = base1 + r1[tid] - c1;

    float s00 = 0.f, s01 = 0.f, s10 = 0.f, s11 = 0.f;
    const float2* p0 = g_q0 + off0;
    #pragma unroll 4
    for (int i = 0; i < c0; i++) { float2 v = p0[i]; s00 += v.x; s01 += v.y; }
    const float2* p1 = g_q1 + off1;
    #pragma unroll 4
    for (int i = 0; i < c1; i++) { float2 v = p1[i]; s10 += v.x; s11 += v.y; }

    const float n0 = 1.0f / (dm0[a] * 32.f);
    const float n1 = 1.0f / (dm1[a] * 32.f);
    out[2 * a]     = b2[0] + s00 * n0 + s10 * n1;
    out[2 * a + 1] = b2[1] + s01 * n0 + s11 * n1;
}

// ---------------------------------------------------------------------------
extern "C" void kernel_launch(void* const* d_in, const int* in_sizes, int n_in,
                              void* d_out, int out_size) {
    const float* t0  = (const float*)d_in[0];
    const float* t1  = (const float*)d_in[1];
    const float* W0  = (const float*)d_in[2];
    const float* b0  = (const float*)d_in[3];
    const float* W1  = (const float*)d_in[4];
    const float* b1  = (const float*)d_in[5];
    const float* W2  = (const float*)d_in[6];
    const float* b2  = (const float*)d_in[7];
    const int*   c0  = (const int*)d_in[8];
    const int*   c1  = (const int*)d_in[9];
    const float* dm0 = (const float*)d_in[11];
    const float* dm1 = (const float*)d_in[12];
    float* out = (float*)d_out;

    const int A = in_sizes[8];
    const int R = in_sizes[0] / 384;   // reads per source (C*L = 384)

    dim3 grid1(1024, 2);
    rc_phase1<<<grid1, 256>>>(t0, t1, W0, b0, W1, b1, W2, R);
    rc_phase2<<<(A + 255) / 256, 256>>>(c0, c1, dm0, dm1, b2, out, A);
}